// round 16
// baseline (speedup 1.0000x reference)
#include <cuda_runtime.h>
#include <cuda_bf16.h>
#include <math_constants.h>
#include <cstdint>

typedef __nv_bfloat16 bf16;

#define B_   2
#define S_   2048
#define D_   1024
#define H_   16
#define HD_  64
#define M_   (B_ * S_)

#define QSCALE 0.18033688011112042f
#define PROJ_SPIN 1400

__device__ __forceinline__ uint32_t smem_to_u32(const void* p) {
    uint32_t a;
    asm("{ .reg .u64 t; cvta.to.shared.u64 t, %1; cvt.u32.u64 %0, t; }" : "=r"(a) : "l"(p));
    return a;
}

#define SWZ(x) ((uint32_t)(x) ^ ((((uint32_t)(x)) >> 3) & 0x70))

#define CPA(dst, src) \
    asm volatile("cp.async.cg.shared.global [%0], [%1], 16;" :: "r"(dst), "l"(src))
#define CPC() asm volatile("cp.async.commit_group;" ::: "memory")
#define CPW(N) asm volatile("cp.async.wait_group %0;" :: "n"(N) : "memory")

#define LDSM4(r0, r1, r2, r3, addr) \
    asm volatile("ldmatrix.sync.aligned.m8n8.x4.shared.b16 {%0,%1,%2,%3}, [%4];" \
        : "=r"(r0), "=r"(r1), "=r"(r2), "=r"(r3) : "r"(addr))
#define LDSM4T(r0, r1, r2, r3, addr) \
    asm volatile("ldmatrix.sync.aligned.m8n8.x4.trans.shared.b16 {%0,%1,%2,%3}, [%4];" \
        : "=r"(r0), "=r"(r1), "=r"(r2), "=r"(r3) : "r"(addr))

#define MMA(d, a, b0, b1) \
    asm volatile("mma.sync.aligned.m16n8k16.row.col.f32.bf16.bf16.f32 " \
        "{%0,%1,%2,%3},{%4,%5,%6,%7},{%8,%9},{%0,%1,%2,%3};" \
        : "+f"((d)[0]), "+f"((d)[1]), "+f"((d)[2]), "+f"((d)[3]) \
        : "r"((a)[0]), "r"((a)[1]), "r"((a)[2]), "r"((a)[3]), "r"(b0), "r"(b1))

__device__ __forceinline__ float ex2(float x) {
    float y;
    asm("ex2.approx.ftz.f32 %0, %1;" : "=f"(y) : "f"(x));
    return y;
}

__device__ __forceinline__ void split2(float a, float b, uint32_t& hi, uint32_t& lo) {
    uint32_t h;
    asm("cvt.rn.bf16x2.f32 %0, %1, %2;" : "=r"(h) : "f"(b), "f"(a));
    float fa = __uint_as_float(h << 16);
    float fb = __uint_as_float(h & 0xffff0000u);
    uint32_t l;
    asm("cvt.rn.bf16x2.f32 %0, %1, %2;" : "=r"(l) : "f"(b - fb), "f"(a - fa));
    hi = h; lo = l;
}

__device__ __forceinline__ int ldacq(const int* p) {
    int v;
    asm volatile("ld.acquire.gpu.global.b32 %0, [%1];" : "=r"(v) : "l"(p));
    return v;
}

// ---------------------------------------------------------------------------
// cross-stage completion flags + stagger tickets (reset each launch)
// ---------------------------------------------------------------------------
__device__ int g_fq[256];   // [mtile 0..31][ntile 0..7]  Q proj done
__device__ int g_fkv[16];   // [b 0..1][ntile 0..7]       K+V proj done (target 32)
__device__ int g_fa[32];    // [mtile 0..31]              attn rows done (target 16)
__device__ int g_tix[768];

__device__ __forceinline__ void waitflag(const int* p, int target) {
    if (threadIdx.x == 0) {
        while (ldacq(p) < target) __nanosleep(128);
    }
    __syncthreads();
}

__device__ __forceinline__ void stagger(int* slot, int tid, int base, int spin) {
    if (tid == 0) {
        uint32_t smid;
        asm("mov.u32 %0, %%smid;" : "=r"(smid));
        slot[0] = atomicAdd(&g_tix[base + smid], 1);
    }
    __syncthreads();
    if (slot[0] & 1) {
        unsigned long long s0 = clock64();
        while (clock64() - s0 < (unsigned long long)spin) {}
    }
}

// ---------------------------------------------------------------------------
// Scratch
// ---------------------------------------------------------------------------
__device__ bf16 g_xh[M_ * D_],  g_xl[M_ * D_];
__device__ bf16 g_wh[4][D_ * D_], g_wl[4][D_ * D_];
__device__ bf16 g_qh[M_ * D_],  g_ql[M_ * D_];
__device__ bf16 g_kh[M_ * D_],  g_kl[M_ * D_];
__device__ bf16 g_vh[M_ * D_],  g_vl[M_ * D_];
__device__ bf16 g_ah[M_ * D_],  g_al[M_ * D_];

// ---------------------------------------------------------------------------
// fused conversion kernel: y==0 -> x split (+flag reset in block 0); y>=1 -> weights
// ---------------------------------------------------------------------------
struct CvtAll { const float* x; const float* w[4]; bf16 *xh, *xl, *wh, *wl; };

__global__ __launch_bounds__(256) void cvt_all(CvtAll C)
{
    const int tid = threadIdx.x;
    if (blockIdx.y == 0) {
        if (blockIdx.x == 0) {
            for (int i = tid; i < 256; i += 256) g_fq[i] = 0;
            if (tid < 16) g_fkv[tid] = 0;
            if (tid < 32) g_fa[tid] = 0;
            for (int i = tid; i < 768; i += 256) g_tix[i] = 0;
        }
        int i = blockIdx.x * 256 + tid;
        if (i >= M_ * D_ / 4) return;
        float4 v = ((const float4*)C.x)[i];
        uint32_t h0, h1, l0, l1;
        split2(v.x, v.y, h0, l0);
        split2(v.z, v.w, h1, l1);
        ((uint2*)C.xh)[i] = make_uint2(h0, h1);
        ((uint2*)C.xl)[i] = make_uint2(l0, l1);
    } else {
        const int z = blockIdx.y - 1;
        int i = blockIdx.x * 256 + tid;
        if (i >= D_ * D_ / 4) return;
        float4 v = ((const float4*)C.w[z])[i];
        uint32_t h0, h1, l0, l1;
        split2(v.x, v.y, h0, l0);
        split2(v.z, v.w, h1, l1);
        ((uint2*)(C.wh + (size_t)z * D_ * D_))[i] = make_uint2(h0, h1);
        ((uint2*)(C.wl + (size_t)z * D_ * D_))[i] = make_uint2(l0, l1);
    }
}

// ---------------------------------------------------------------------------
// proj body (fat warps, 128 threads): C[m0:+128, n0:+128] = A @ W^T + bias
// ---------------------------------------------------------------------------
#define PJ_SMEM (3 * 32768 + 512 + 16)

__device__ void proj_body(char* smem,
    const bf16* __restrict__ Ah, const bf16* __restrict__ Al,
    const bf16* __restrict__ Wh, const bf16* __restrict__ Wl,
    const float* __restrict__ bias,
    bf16* __restrict__ Oh, bf16* __restrict__ Ol, float* __restrict__ Ofp,
    float scv, int mode, int m0, int n0, int tixbase)
{
    float* bsm = (float*)(smem + 3 * 32768);
    int* stk = (int*)(smem + 3 * 32768 + 512);
    const uint32_t sb = smem_to_u32(smem);
    const int tid = threadIdx.x, lane = tid & 31, wid = tid >> 5;

    bsm[tid] = bias[n0 + tid];

    const int lr = tid >> 3, lc = tid & 7;

    auto ISSUE = [&](int c) {
        if (c < 48) {
            const int seg = c >> 4, kb = (c & 15) * 64;
            const bf16* As = (seg < 2) ? Ah : Al;
            const bf16* Ws = (seg == 1) ? Wl : Wh;
            const uint32_t stg = sb + (c % 3) * 32768;
#pragma unroll
            for (int i = 0; i < 8; i++) {
                int row = lr + i * 16;
                uint32_t off = SWZ(row * 128 + lc * 16);
                CPA(stg + off,         As + (size_t)(m0 + row) * D_ + kb + lc * 8);
                CPA(stg + 16384 + off, Ws + (size_t)(n0 + row) * D_ + kb + lc * 8);
            }
        }
        CPC();
    };
    ISSUE(0); ISSUE(1);

    stagger(stk, tid, tixbase, PROJ_SPIN);

    const int wm = wid >> 1, wn = wid & 1;
    const int part = lane >> 3;
    float acc[4][8][4];
#pragma unroll
    for (int a = 0; a < 4; a++)
#pragma unroll
        for (int bnt = 0; bnt < 8; bnt++)
#pragma unroll
            for (int e = 0; e < 4; e++) acc[a][bnt][e] = 0.f;

    for (int c = 0; c < 48; c++) {
        CPW(1);
        __syncthreads();
        ISSUE(c + 2);
        const uint32_t aB = sb + (c % 3) * 32768, wB = aB + 16384;
#pragma unroll
        for (int ks = 0; ks < 4; ks++) {
            uint32_t af[4][4];
#pragma unroll
            for (int mt = 0; mt < 4; mt++) {
                int row = wm * 64 + mt * 16 + (lane & 15);
                int kb2 = ks * 16 + (lane >> 4) * 8;
                LDSM4(af[mt][0], af[mt][1], af[mt][2], af[mt][3], aB + SWZ(row * 128 + kb2 * 2));
            }
            const int kb2 = ks * 16 + ((part & 1) << 3);
#pragma unroll
            for (int gg = 0; gg < 4; gg++) {
                int nrow = wn * 64 + gg * 16 + ((part >> 1) << 3) + (lane & 7);
                uint32_t b0, b1, b2, b3;
                LDSM4(b0, b1, b2, b3, wB + SWZ(nrow * 128 + kb2 * 2));
#pragma unroll
                for (int mt = 0; mt < 4; mt++) {
                    MMA(acc[mt][2 * gg],     af[mt], b0, b1);
                    MMA(acc[mt][2 * gg + 1], af[mt], b2, b3);
                }
            }
        }
    }

    const int g = lane >> 2, t4 = lane & 3;
#pragma unroll
    for (int mt = 0; mt < 4; mt++) {
        int r0 = m0 + wm * 64 + mt * 16 + g;
#pragma unroll
        for (int nt = 0; nt < 8; nt++) {
            int cloc = wn * 64 + nt * 8 + t4 * 2;
            float b0v = bsm[cloc], b1v = bsm[cloc + 1];
            float v0 = (acc[mt][nt][0] + b0v) * scv, v1 = (acc[mt][nt][1] + b1v) * scv;
            float v2 = (acc[mt][nt][2] + b0v) * scv, v3 = (acc[mt][nt][3] + b1v) * scv;
            size_t o0 = (size_t)r0 * D_ + n0 + cloc;
            size_t o1 = o0 + 8 * (size_t)D_;
            if (mode == 1) {
                *(float2*)(Ofp + o0) = make_float2(v0, v1);
                *(float2*)(Ofp + o1) = make_float2(v2, v3);
            } else {
                uint32_t hh, ll;
                split2(v0, v1, hh, ll);
                *(uint32_t*)(Oh + o0) = hh; *(uint32_t*)(Ol + o0) = ll;
                split2(v2, v3, hh, ll);
                *(uint32_t*)(Oh + o1) = hh; *(uint32_t*)(Ol + o1) = ll;
            }
        }
    }
}

// ---------------------------------------------------------------------------
// attention body (fat warps, 128 threads, round-15 proven)
// ---------------------------------------------------------------------------
#define NT_ 32

__device__ void attn_body(char* smem,
    const bf16* __restrict__ Qh, const bf16* __restrict__ Ql,
    const bf16* __restrict__ Kh, const bf16* __restrict__ Kl,
    const bf16* __restrict__ Vh, const bf16* __restrict__ Vl,
    bf16* __restrict__ Oh, bf16* __restrict__ Ol,
    int b, int h, int q0)
{
    const uint32_t sb = smem_to_u32(smem);
    const int tid = threadIdx.x, lane = tid & 31, wid = tid >> 5;
    const int lr = tid >> 3, lc = tid & 7;
    const int wrow = wid * 32;
    const int part = lane >> 3;

#pragma unroll
    for (int i = 0; i < 8; i++) {
        int row = lr + i * 16;
        uint32_t off = SWZ(row * 128 + lc * 16);
        size_t gq = (size_t)(b * S_ + q0 + row) * D_ + h * 64 + lc * 8;
        CPA(sb + off,         Qh + gq);
        CPA(sb + 16384 + off, Ql + gq);
    }

    auto ISSUE = [&](int t) {
        if (t < NT_) {
            const int k0 = t * 64;
            const uint32_t st = sb + 32768 + (t & 1) * 32768;
#pragma unroll
            for (int i = 0; i < 4; i++) {
                int row = lr + i * 16;
                uint32_t off = SWZ(row * 128 + lc * 16);
                size_t gk = (size_t)(b * S_ + k0 + row) * D_ + h * 64 + lc * 8;
                CPA(st + off,         Kh + gk);
                CPA(st + 8192 + off,  Kl + gk);
                CPA(st + 16384 + off, Vh + gk);
                CPA(st + 24576 + off, Vl + gk);
            }
        }
        CPC();
    };
    ISSUE(0); ISSUE(1);

    float o[2][8][4];
#pragma unroll
    for (int mt = 0; mt < 2; mt++)
#pragma unroll
        for (int nt = 0; nt < 8; nt++)
#pragma unroll
            for (int e = 0; e < 4; e++) o[mt][nt][e] = 0.f;
    float mr[4] = {-CUDART_INF_F, -CUDART_INF_F, -CUDART_INF_F, -CUDART_INF_F};
    float lv[4] = {0.f, 0.f, 0.f, 0.f};
    const int g = lane >> 2, t4 = lane & 3;

    for (int t = 0; t < NT_; t++) {
        CPW(1);
        __syncthreads();
        const uint32_t kH = sb + 32768 + (t & 1) * 32768;
        const uint32_t kL = kH + 8192, vH = kH + 16384, vL = kH + 24576;

        float sc[2][8][4];
#pragma unroll
        for (int mt = 0; mt < 2; mt++)
#pragma unroll
            for (int nt = 0; nt < 8; nt++)
#pragma unroll
                for (int e = 0; e < 4; e++) sc[mt][nt][e] = 0.f;

#pragma unroll
        for (int ks = 0; ks < 4; ks++) {
            uint32_t aH[2][4], aL[2][4];
#pragma unroll
            for (int mt = 0; mt < 2; mt++) {
                int row = wrow + mt * 16 + (lane & 15);
                int kb2 = ks * 16 + (lane >> 4) * 8;
                uint32_t off = SWZ(row * 128 + kb2 * 2);
                LDSM4(aH[mt][0], aH[mt][1], aH[mt][2], aH[mt][3], sb + off);
                LDSM4(aL[mt][0], aL[mt][1], aL[mt][2], aL[mt][3], sb + 16384 + off);
            }
#pragma unroll
            for (int gg = 0; gg < 4; gg++) {
                int nrow = gg * 16 + ((part >> 1) << 3) + (lane & 7);
                int kb2 = ks * 16 + ((part & 1) << 3);
                uint32_t off = SWZ(nrow * 128 + kb2 * 2);
                uint32_t b0, b1, b2, b3;
                LDSM4(b0, b1, b2, b3, kH + off);
#pragma unroll
                for (int mt = 0; mt < 2; mt++) {
                    MMA(sc[mt][2 * gg],     aH[mt], b0, b1);
                    MMA(sc[mt][2 * gg + 1], aH[mt], b2, b3);
                    MMA(sc[mt][2 * gg],     aL[mt], b0, b1);
                    MMA(sc[mt][2 * gg + 1], aL[mt], b2, b3);
                }
                LDSM4(b0, b1, b2, b3, kL + off);
#pragma unroll
                for (int mt = 0; mt < 2; mt++) {
                    MMA(sc[mt][2 * gg],     aH[mt], b0, b1);
                    MMA(sc[mt][2 * gg + 1], aH[mt], b2, b3);
                }
            }
        }

#pragma unroll
        for (int mt = 0; mt < 2; mt++) {
            float mx0 = -CUDART_INF_F, mx1 = -CUDART_INF_F;
#pragma unroll
            for (int nt = 0; nt < 8; nt++) {
                mx0 = fmaxf(mx0, fmaxf(sc[mt][nt][0], sc[mt][nt][1]));
                mx1 = fmaxf(mx1, fmaxf(sc[mt][nt][2], sc[mt][nt][3]));
            }
            mx0 = fmaxf(mx0, __shfl_xor_sync(0xffffffffu, mx0, 1));
            mx0 = fmaxf(mx0, __shfl_xor_sync(0xffffffffu, mx0, 2));
            mx1 = fmaxf(mx1, __shfl_xor_sync(0xffffffffu, mx1, 1));
            mx1 = fmaxf(mx1, __shfl_xor_sync(0xffffffffu, mx1, 2));
            const float mn0 = fmaxf(mr[2 * mt], mx0), mn1 = fmaxf(mr[2 * mt + 1], mx1);
            const float al0 = ex2(mr[2 * mt] - mn0), al1 = ex2(mr[2 * mt + 1] - mn1);
            float s0 = 0.f, s1 = 0.f;
#pragma unroll
            for (int nt = 0; nt < 8; nt++) {
                sc[mt][nt][0] = ex2(sc[mt][nt][0] - mn0); s0 += sc[mt][nt][0];
                sc[mt][nt][1] = ex2(sc[mt][nt][1] - mn0); s0 += sc[mt][nt][1];
                sc[mt][nt][2] = ex2(sc[mt][nt][2] - mn1); s1 += sc[mt][nt][2];
                sc[mt][nt][3] = ex2(sc[mt][nt][3] - mn1); s1 += sc[mt][nt][3];
            }
            s0 += __shfl_xor_sync(0xffffffffu, s0, 1);
            s0 += __shfl_xor_sync(0xffffffffu, s0, 2);
            s1 += __shfl_xor_sync(0xffffffffu, s1, 1);
            s1 += __shfl_xor_sync(0xffffffffu, s1, 2);
            lv[2 * mt] = lv[2 * mt] * al0 + s0;
            lv[2 * mt + 1] = lv[2 * mt + 1] * al1 + s1;
            mr[2 * mt] = mn0; mr[2 * mt + 1] = mn1;
#pragma unroll
            for (int nt = 0; nt < 8; nt++) {
                o[mt][nt][0] *= al0; o[mt][nt][1] *= al0;
                o[mt][nt][2] *= al1; o[mt][nt][3] *= al1;
            }
        }

#pragma unroll
        for (int j = 0; j < 4; j++) {
            uint32_t ph[2][4], pl[2][4];
#pragma unroll
            for (int mt = 0; mt < 2; mt++) {
                split2(sc[mt][2 * j][0],     sc[mt][2 * j][1],     ph[mt][0], pl[mt][0]);
                split2(sc[mt][2 * j][2],     sc[mt][2 * j][3],     ph[mt][1], pl[mt][1]);
                split2(sc[mt][2 * j + 1][0], sc[mt][2 * j + 1][1], ph[mt][2], pl[mt][2]);
                split2(sc[mt][2 * j + 1][2], sc[mt][2 * j + 1][3], ph[mt][3], pl[mt][3]);
            }
            int krow = j * 16 + ((part & 1) << 3) + (lane & 7);
#pragma unroll
            for (int g16 = 0; g16 < 4; g16++) {
                int nb = g16 * 16 + ((part >> 1) << 3);
                uint32_t off = SWZ(krow * 128 + nb * 2);
                uint32_t v0, v1, v2, v3;
                LDSM4T(v0, v1, v2, v3, vH + off);
#pragma unroll
                for (int mt = 0; mt < 2; mt++) {
                    MMA(o[mt][2 * g16],     ph[mt], v0, v1);
                    MMA(o[mt][2 * g16 + 1], ph[mt], v2, v3);
                    MMA(o[mt][2 * g16],     pl[mt], v0, v1);
                    MMA(o[mt][2 * g16 + 1], pl[mt], v2, v3);
                }
                LDSM4T(v0, v1, v2, v3, vL + off);
#pragma unroll
                for (int mt = 0; mt < 2; mt++) {
                    MMA(o[mt][2 * g16],     ph[mt], v0, v1);
                    MMA(o[mt][2 * g16 + 1], ph[mt], v2, v3);
                }
            }
        }
        __syncthreads();
        ISSUE(t + 2);
    }

#pragma unroll
    for (int mt = 0; mt < 2; mt++) {
        const float i0 = 1.f / lv[2 * mt], i1 = 1.f / lv[2 * mt + 1];
        const int r0 = q0 + wrow + mt * 16 + g, r1 = r0 + 8;
#pragma unroll
        for (int nt = 0; nt < 8; nt++) {
            int col = h * 64 + nt * 8 + t4 * 2;
            uint32_t hh, ll;
            split2(o[mt][nt][0] * i0, o[mt][nt][1] * i0, hh, ll);
            size_t o0 = (size_t)(b * S_ + r0) * D_ + col;
            *(uint32_t*)(Oh + o0) = hh; *(uint32_t*)(Ol + o0) = ll;
            split2(o[mt][nt][2] * i1, o[mt][nt][3] * i1, hh, ll);
            size_t o1 = (size_t)(b * S_ + r1) * D_ + col;
            *(uint32_t*)(Oh + o1) = hh; *(uint32_t*)(Ol + o1) = ll;
        }
    }
}

// ---------------------------------------------------------------------------
// MEGA kernel: bid 0..767 proj-QKV | 768..1279 attn | 1280..1535 proj-O
// Cross-stage dependencies via device-scope flags (dispatch order = bid order).
// ---------------------------------------------------------------------------
struct MegaP {
    const bf16 *xh, *xl, *wh, *wl;
    const float *bq, *bk, *bv, *bo;
    bf16 *qh, *ql, *kh, *kl, *vh, *vl, *ah, *al;
    float *out;
};

__global__ __launch_bounds__(128, 2) void mega(MegaP P)
{
    extern __shared__ char smem[];
    const int bid = blockIdx.x;
    const int tid = threadIdx.x;
    const int WN = D_ * D_;

    if (bid < 768) {
        // ---- QKV projection
        const int z = bid >> 8, r = bid & 255;
        const int n0 = (r & 7) * 128, m0 = (r >> 3) * 128;
        const bf16* Wh = P.wh + (size_t)z * WN;
        const bf16* Wl = P.wl + (size_t)z * WN;
        const float* bias = (z == 0) ? P.bq : (z == 1) ? P.bk : P.bv;
        bf16* Oh = (z == 0) ? P.qh : (z == 1) ? P.kh : P.vh;
        bf16* Ol = (z == 0) ? P.ql : (z == 1) ? P.kl : P.vl;
        const float sc = (z == 0) ? QSCALE : 1.f;
        proj_body(smem, P.xh, P.xl, Wh, Wl, bias, Oh, Ol, nullptr, sc, 0, m0, n0, 0);
        __threadfence();
        __syncthreads();
        if (tid == 0) {
            if (z == 0) atomicAdd(&g_fq[(m0 >> 7) * 8 + (n0 >> 7)], 1);
            else        atomicAdd(&g_fkv[(m0 >> 11) * 8 + (n0 >> 7)], 1);
        }
    } else if (bid < 1280) {
        // ---- attention
        const int id = bid - 768;
        const int qt = id & 15, h = (id >> 4) & 15, b = id >> 8;
        const int my = b * 16 + qt, nt = h >> 1;
        waitflag(&g_fq[my * 8 + nt], 1);
        waitflag(&g_fkv[b * 8 + nt], 32);
        attn_body(smem, P.qh, P.ql, P.kh, P.kl, P.vh, P.vl, P.ah, P.al, b, h, qt * 128);
        __threadfence();
        __syncthreads();
        if (tid == 0) atomicAdd(&g_fa[my], 1);
    } else {
        // ---- output projection
        const int id = bid - 1280;
        const int n0 = (id & 7) * 128, my = id >> 3, m0 = my * 128;
        waitflag(&g_fa[my], 16);
        proj_body(smem, P.ah, P.al, P.wh + (size_t)3 * WN, P.wl + (size_t)3 * WN,
                  P.bo, nullptr, nullptr, P.out, 1.f, 1, m0, n0, 256);
    }
}

// ---------------------------------------------------------------------------
// Launch
// ---------------------------------------------------------------------------
extern "C" void kernel_launch(void* const* d_in, const int* in_sizes, int n_in,
                              void* d_out, int out_size)
{
    const float* x  = (const float*)d_in[0];
    const float* Wq = (const float*)d_in[1];
    const float* bq = (const float*)d_in[2];
    const float* Wk = (const float*)d_in[3];
    const float* bk = (const float*)d_in[4];
    const float* Wv = (const float*)d_in[5];
    const float* bv = (const float*)d_in[6];
    const float* Wo = (const float*)d_in[7];
    const float* bo = (const float*)d_in[8];
    float* out = (float*)d_out;

    bf16 *xh, *xl, *wh, *wl, *qh, *ql, *kh, *kl, *vh, *vl, *ah, *al;
    cudaGetSymbolAddress((void**)&xh, g_xh); cudaGetSymbolAddress((void**)&xl, g_xl);
    cudaGetSymbolAddress((void**)&wh, g_wh); cudaGetSymbolAddress((void**)&wl, g_wl);
    cudaGetSymbolAddress((void**)&qh, g_qh); cudaGetSymbolAddress((void**)&ql, g_ql);
    cudaGetSymbolAddress((void**)&kh, g_kh); cudaGetSymbolAddress((void**)&kl, g_kl);
    cudaGetSymbolAddress((void**)&vh, g_vh); cudaGetSymbolAddress((void**)&vl, g_vl);
    cudaGetSymbolAddress((void**)&ah, g_ah); cudaGetSymbolAddress((void**)&al, g_al);

    // conversions + flag reset (one launch)
    {
        CvtAll C;
        C.x = x;
        C.w[0] = Wq; C.w[1] = Wk; C.w[2] = Wv; C.w[3] = Wo;
        C.xh = xh; C.xl = xl; C.wh = wh; C.wl = wl;
        dim3 g(M_ * D_ / 4 / 256, 5);
        cvt_all<<<g, 256>>>(C);
    }

    cudaFuncSetAttribute(mega, cudaFuncAttributeMaxDynamicSharedMemorySize, PJ_SMEM);

    {
        MegaP P;
        P.xh = xh; P.xl = xl; P.wh = wh; P.wl = wl;
        P.bq = bq; P.bk = bk; P.bv = bv; P.bo = bo;
        P.qh = qh; P.ql = ql; P.kh = kh; P.kl = kl;
        P.vh = vh; P.vl = vl; P.ah = ah; P.al = al;
        P.out = out;
        mega<<<1536, 128, PJ_SMEM>>>(P);
    }
}

// round 17
// speedup vs baseline: 1.0630x; 1.0630x over previous
#include <cuda_runtime.h>
#include <cuda_bf16.h>
#include <math_constants.h>
#include <cstdint>

typedef __nv_bfloat16 bf16;

#define B_   2
#define S_   2048
#define D_   1024
#define H_   16
#define HD_  64
#define M_   (B_ * S_)

#define QSCALE 0.18033688011112042f
#define PROJ_SPIN 1400

__device__ __forceinline__ uint32_t smem_to_u32(const void* p) {
    uint32_t a;
    asm("{ .reg .u64 t; cvta.to.shared.u64 t, %1; cvt.u32.u64 %0, t; }" : "=r"(a) : "l"(p));
    return a;
}

#define SWZ(x) ((uint32_t)(x) ^ ((((uint32_t)(x)) >> 3) & 0x70))

#define CPA(dst, src) \
    asm volatile("cp.async.cg.shared.global [%0], [%1], 16;" :: "r"(dst), "l"(src))
#define CPC() asm volatile("cp.async.commit_group;" ::: "memory")
#define CPW(N) asm volatile("cp.async.wait_group %0;" :: "n"(N) : "memory")

#define LDSM4(r0, r1, r2, r3, addr) \
    asm volatile("ldmatrix.sync.aligned.m8n8.x4.shared.b16 {%0,%1,%2,%3}, [%4];" \
        : "=r"(r0), "=r"(r1), "=r"(r2), "=r"(r3) : "r"(addr))
#define LDSM4T(r0, r1, r2, r3, addr) \
    asm volatile("ldmatrix.sync.aligned.m8n8.x4.trans.shared.b16 {%0,%1,%2,%3}, [%4];" \
        : "=r"(r0), "=r"(r1), "=r"(r2), "=r"(r3) : "r"(addr))

#define MMA(d, a, b0, b1) \
    asm volatile("mma.sync.aligned.m16n8k16.row.col.f32.bf16.bf16.f32 " \
        "{%0,%1,%2,%3},{%4,%5,%6,%7},{%8,%9},{%0,%1,%2,%3};" \
        : "+f"((d)[0]), "+f"((d)[1]), "+f"((d)[2]), "+f"((d)[3]) \
        : "r"((a)[0]), "r"((a)[1]), "r"((a)[2]), "r"((a)[3]), "r"(b0), "r"(b1))

__device__ __forceinline__ float ex2(float x) {
    float y;
    asm("ex2.approx.ftz.f32 %0, %1;" : "=f"(y) : "f"(x));
    return y;
}

__device__ __forceinline__ void split2(float a, float b, uint32_t& hi, uint32_t& lo) {
    uint32_t h;
    asm("cvt.rn.bf16x2.f32 %0, %1, %2;" : "=r"(h) : "f"(b), "f"(a));
    float fa = __uint_as_float(h << 16);
    float fb = __uint_as_float(h & 0xffff0000u);
    uint32_t l;
    asm("cvt.rn.bf16x2.f32 %0, %1, %2;" : "=r"(l) : "f"(b - fb), "f"(a - fa));
    hi = h; lo = l;
}

__device__ __forceinline__ int ldacq(const int* p) {
    int v;
    asm volatile("ld.acquire.gpu.global.b32 %0, [%1];" : "=r"(v) : "l"(p));
    return v;
}

// ---------------------------------------------------------------------------
// cross-stage completion flags + stagger tickets (reset each launch)
// ---------------------------------------------------------------------------
__device__ int g_fq[256];   // [mtile 0..31][ntile 0..7]  Q proj done (target 1)
__device__ int g_fkv[16];   // [b 0..1][ntile 0..7]       K+V proj done (target 32)
__device__ int g_fa[32];    // [mtile 0..31]              attn rows done (target 16)
__device__ int g_tix[768];

__device__ __forceinline__ void waitflag(const int* p, int target) {
    if (threadIdx.x == 0) {
        while (ldacq(p) < target) __nanosleep(128);
    }
    __syncthreads();
}

__device__ __forceinline__ void stagger(int* slot, int tid, int base, int spin) {
    if (tid == 0) {
        uint32_t smid;
        asm("mov.u32 %0, %%smid;" : "=r"(smid));
        slot[0] = atomicAdd(&g_tix[base + smid], 1);
    }
    __syncthreads();
    if (slot[0] & 1) {
        unsigned long long s0 = clock64();
        while (clock64() - s0 < (unsigned long long)spin) {}
    }
}

// ---------------------------------------------------------------------------
// Scratch
// ---------------------------------------------------------------------------
__device__ bf16 g_xh[M_ * D_],  g_xl[M_ * D_];
__device__ bf16 g_wh[4][D_ * D_], g_wl[4][D_ * D_];
__device__ bf16 g_qh[M_ * D_],  g_ql[M_ * D_];
__device__ bf16 g_kh[M_ * D_],  g_kl[M_ * D_];
__device__ bf16 g_vh[M_ * D_],  g_vl[M_ * D_];
__device__ bf16 g_ah[M_ * D_],  g_al[M_ * D_];

// ---------------------------------------------------------------------------
// x conversion (+ flag reset in block 0)
// ---------------------------------------------------------------------------
__global__ __launch_bounds__(256) void cvt_kernel(const float* __restrict__ in,
                                                  bf16* __restrict__ hi, bf16* __restrict__ lo, int n4)
{
    const int tid = threadIdx.x;
    if (blockIdx.x == 0) {
        g_fq[tid] = 0;
        if (tid < 16) g_fkv[tid] = 0;
        if (tid < 32) g_fa[tid] = 0;
        for (int i = tid; i < 768; i += 256) g_tix[i] = 0;
    }
    int i = blockIdx.x * 256 + tid;
    if (i >= n4) return;
    float4 v = ((const float4*)in)[i];
    uint32_t h0, h1, l0, l1;
    split2(v.x, v.y, h0, l0);
    split2(v.z, v.w, h1, l1);
    ((uint2*)hi)[i] = make_uint2(h0, h1);
    ((uint2*)lo)[i] = make_uint2(l0, l1);
}

// 4 weight matrices, one launch (z selects source)
struct CvtW { const float* src[4]; bf16 *hi, *lo; };
__global__ __launch_bounds__(256) void cvtw_kernel(CvtW P)
{
    const int n4 = D_ * D_ / 4;
    int i = blockIdx.x * 256 + threadIdx.x;
    if (i >= n4) return;
    const int z = blockIdx.y;
    float4 v = ((const float4*)P.src[z])[i];
    uint32_t h0, h1, l0, l1;
    split2(v.x, v.y, h0, l0);
    split2(v.z, v.w, h1, l1);
    ((uint2*)(P.hi + (size_t)z * D_ * D_))[i] = make_uint2(h0, h1);
    ((uint2*)(P.lo + (size_t)z * D_ * D_))[i] = make_uint2(l0, l1);
}

// ---------------------------------------------------------------------------
// proj body (fat warps, 128 threads): C[m0:+128, n0:+128] = A @ W^T + bias
// ---------------------------------------------------------------------------
#define PJ_SMEM (3 * 32768 + 512 + 16)

__device__ void proj_body(char* smem,
    const bf16* __restrict__ Ah, const bf16* __restrict__ Al,
    const bf16* __restrict__ Wh, const bf16* __restrict__ Wl,
    const float* __restrict__ bias,
    bf16* __restrict__ Oh, bf16* __restrict__ Ol, float* __restrict__ Ofp,
    float scv, int mode, int m0, int n0, int tixbase)
{
    float* bsm = (float*)(smem + 3 * 32768);
    int* stk = (int*)(smem + 3 * 32768 + 512);
    const uint32_t sb = smem_to_u32(smem);
    const int tid = threadIdx.x, lane = tid & 31, wid = tid >> 5;

    bsm[tid] = bias[n0 + tid];

    const int lr = tid >> 3, lc = tid & 7;

    auto ISSUE = [&](int c) {
        if (c < 48) {
            const int seg = c >> 4, kb = (c & 15) * 64;
            const bf16* As = (seg < 2) ? Ah : Al;
            const bf16* Ws = (seg == 1) ? Wl : Wh;
            const uint32_t stg = sb + (c % 3) * 32768;
#pragma unroll
            for (int i = 0; i < 8; i++) {
                int row = lr + i * 16;
                uint32_t off = SWZ(row * 128 + lc * 16);
                CPA(stg + off,         As + (size_t)(m0 + row) * D_ + kb + lc * 8);
                CPA(stg + 16384 + off, Ws + (size_t)(n0 + row) * D_ + kb + lc * 8);
            }
        }
        CPC();
    };
    ISSUE(0); ISSUE(1);

    stagger(stk, tid, tixbase, PROJ_SPIN);

    const int wm = wid >> 1, wn = wid & 1;
    const int part = lane >> 3;
    float acc[4][8][4];
#pragma unroll
    for (int a = 0; a < 4; a++)
#pragma unroll
        for (int bnt = 0; bnt < 8; bnt++)
#pragma unroll
            for (int e = 0; e < 4; e++) acc[a][bnt][e] = 0.f;

    for (int c = 0; c < 48; c++) {
        CPW(1);
        __syncthreads();
        ISSUE(c + 2);
        const uint32_t aB = sb + (c % 3) * 32768, wB = aB + 16384;
#pragma unroll
        for (int ks = 0; ks < 4; ks++) {
            uint32_t af[4][4];
#pragma unroll
            for (int mt = 0; mt < 4; mt++) {
                int row = wm * 64 + mt * 16 + (lane & 15);
                int kb2 = ks * 16 + (lane >> 4) * 8;
                LDSM4(af[mt][0], af[mt][1], af[mt][2], af[mt][3], aB + SWZ(row * 128 + kb2 * 2));
            }
            const int kb2 = ks * 16 + ((part & 1) << 3);
#pragma unroll
            for (int gg = 0; gg < 4; gg++) {
                int nrow = wn * 64 + gg * 16 + ((part >> 1) << 3) + (lane & 7);
                uint32_t b0, b1, b2, b3;
                LDSM4(b0, b1, b2, b3, wB + SWZ(nrow * 128 + kb2 * 2));
#pragma unroll
                for (int mt = 0; mt < 4; mt++) {
                    MMA(acc[mt][2 * gg],     af[mt], b0, b1);
                    MMA(acc[mt][2 * gg + 1], af[mt], b2, b3);
                }
            }
        }
    }

    const int g = lane >> 2, t4 = lane & 3;
#pragma unroll
    for (int mt = 0; mt < 4; mt++) {
        int r0 = m0 + wm * 64 + mt * 16 + g;
#pragma unroll
        for (int nt = 0; nt < 8; nt++) {
            int cloc = wn * 64 + nt * 8 + t4 * 2;
            float b0v = bsm[cloc], b1v = bsm[cloc + 1];
            float v0 = (acc[mt][nt][0] + b0v) * scv, v1 = (acc[mt][nt][1] + b1v) * scv;
            float v2 = (acc[mt][nt][2] + b0v) * scv, v3 = (acc[mt][nt][3] + b1v) * scv;
            size_t o0 = (size_t)r0 * D_ + n0 + cloc;
            size_t o1 = o0 + 8 * (size_t)D_;
            if (mode == 1) {
                *(float2*)(Ofp + o0) = make_float2(v0, v1);
                *(float2*)(Ofp + o1) = make_float2(v2, v3);
            } else {
                uint32_t hh, ll;
                split2(v0, v1, hh, ll);
                *(uint32_t*)(Oh + o0) = hh; *(uint32_t*)(Ol + o0) = ll;
                split2(v2, v3, hh, ll);
                *(uint32_t*)(Oh + o1) = hh; *(uint32_t*)(Ol + o1) = ll;
            }
        }
    }
}

// ---------------------------------------------------------------------------
// attention body (fat warps, 128 threads)
// ---------------------------------------------------------------------------
#define NT_ 32

__device__ void attn_body(char* smem,
    const bf16* __restrict__ Qh, const bf16* __restrict__ Ql,
    const bf16* __restrict__ Kh, const bf16* __restrict__ Kl,
    const bf16* __restrict__ Vh, const bf16* __restrict__ Vl,
    bf16* __restrict__ Oh, bf16* __restrict__ Ol,
    int b, int h, int q0)
{
    const uint32_t sb = smem_to_u32(smem);
    const int tid = threadIdx.x, lane = tid & 31, wid = tid >> 5;
    const int lr = tid >> 3, lc = tid & 7;
    const int wrow = wid * 32;
    const int part = lane >> 3;

#pragma unroll
    for (int i = 0; i < 8; i++) {
        int row = lr + i * 16;
        uint32_t off = SWZ(row * 128 + lc * 16);
        size_t gq = (size_t)(b * S_ + q0 + row) * D_ + h * 64 + lc * 8;
        CPA(sb + off,         Qh + gq);
        CPA(sb + 16384 + off, Ql + gq);
    }

    auto ISSUE = [&](int t) {
        if (t < NT_) {
            const int k0 = t * 64;
            const uint32_t st = sb + 32768 + (t & 1) * 32768;
#pragma unroll
            for (int i = 0; i < 4; i++) {
                int row = lr + i * 16;
                uint32_t off = SWZ(row * 128 + lc * 16);
                size_t gk = (size_t)(b * S_ + k0 + row) * D_ + h * 64 + lc * 8;
                CPA(st + off,         Kh + gk);
                CPA(st + 8192 + off,  Kl + gk);
                CPA(st + 16384 + off, Vh + gk);
                CPA(st + 24576 + off, Vl + gk);
            }
        }
        CPC();
    };
    ISSUE(0); ISSUE(1);

    float o[2][8][4];
#pragma unroll
    for (int mt = 0; mt < 2; mt++)
#pragma unroll
        for (int nt = 0; nt < 8; nt++)
#pragma unroll
            for (int e = 0; e < 4; e++) o[mt][nt][e] = 0.f;
    float mr[4] = {-CUDART_INF_F, -CUDART_INF_F, -CUDART_INF_F, -CUDART_INF_F};
    float lv[4] = {0.f, 0.f, 0.f, 0.f};
    const int g = lane >> 2, t4 = lane & 3;

    for (int t = 0; t < NT_; t++) {
        CPW(1);
        __syncthreads();
        const uint32_t kH = sb + 32768 + (t & 1) * 32768;
        const uint32_t kL = kH + 8192, vH = kH + 16384, vL = kH + 24576;

        float sc[2][8][4];
#pragma unroll
        for (int mt = 0; mt < 2; mt++)
#pragma unroll
            for (int nt = 0; nt < 8; nt++)
#pragma unroll
                for (int e = 0; e < 4; e++) sc[mt][nt][e] = 0.f;

#pragma unroll
        for (int ks = 0; ks < 4; ks++) {
            uint32_t aH[2][4], aL[2][4];
#pragma unroll
            for (int mt = 0; mt < 2; mt++) {
                int row = wrow + mt * 16 + (lane & 15);
                int kb2 = ks * 16 + (lane >> 4) * 8;
                uint32_t off = SWZ(row * 128 + kb2 * 2);
                LDSM4(aH[mt][0], aH[mt][1], aH[mt][2], aH[mt][3], sb + off);
                LDSM4(aL[mt][0], aL[mt][1], aL[mt][2], aL[mt][3], sb + 16384 + off);
            }
#pragma unroll
            for (int gg = 0; gg < 4; gg++) {
                int nrow = gg * 16 + ((part >> 1) << 3) + (lane & 7);
                int kb2 = ks * 16 + ((part & 1) << 3);
                uint32_t off = SWZ(nrow * 128 + kb2 * 2);
                uint32_t b0, b1, b2, b3;
                LDSM4(b0, b1, b2, b3, kH + off);
#pragma unroll
                for (int mt = 0; mt < 2; mt++) {
                    MMA(sc[mt][2 * gg],     aH[mt], b0, b1);
                    MMA(sc[mt][2 * gg + 1], aH[mt], b2, b3);
                    MMA(sc[mt][2 * gg],     aL[mt], b0, b1);
                    MMA(sc[mt][2 * gg + 1], aL[mt], b2, b3);
                }
                LDSM4(b0, b1, b2, b3, kL + off);
#pragma unroll
                for (int mt = 0; mt < 2; mt++) {
                    MMA(sc[mt][2 * gg],     aH[mt], b0, b1);
                    MMA(sc[mt][2 * gg + 1], aH[mt], b2, b3);
                }
            }
        }

#pragma unroll
        for (int mt = 0; mt < 2; mt++) {
            float mx0 = -CUDART_INF_F, mx1 = -CUDART_INF_F;
#pragma unroll
            for (int nt = 0; nt < 8; nt++) {
                mx0 = fmaxf(mx0, fmaxf(sc[mt][nt][0], sc[mt][nt][1]));
                mx1 = fmaxf(mx1, fmaxf(sc[mt][nt][2], sc[mt][nt][3]));
            }
            mx0 = fmaxf(mx0, __shfl_xor_sync(0xffffffffu, mx0, 1));
            mx0 = fmaxf(mx0, __shfl_xor_sync(0xffffffffu, mx0, 2));
            mx1 = fmaxf(mx1, __shfl_xor_sync(0xffffffffu, mx1, 1));
            mx1 = fmaxf(mx1, __shfl_xor_sync(0xffffffffu, mx1, 2));
            const float mn0 = fmaxf(mr[2 * mt], mx0), mn1 = fmaxf(mr[2 * mt + 1], mx1);
            const float al0 = ex2(mr[2 * mt] - mn0), al1 = ex2(mr[2 * mt + 1] - mn1);
            float s0 = 0.f, s1 = 0.f;
#pragma unroll
            for (int nt = 0; nt < 8; nt++) {
                sc[mt][nt][0] = ex2(sc[mt][nt][0] - mn0); s0 += sc[mt][nt][0];
                sc[mt][nt][1] = ex2(sc[mt][nt][1] - mn0); s0 += sc[mt][nt][1];
                sc[mt][nt][2] = ex2(sc[mt][nt][2] - mn1); s1 += sc[mt][nt][2];
                sc[mt][nt][3] = ex2(sc[mt][nt][3] - mn1); s1 += sc[mt][nt][3];
            }
            s0 += __shfl_xor_sync(0xffffffffu, s0, 1);
            s0 += __shfl_xor_sync(0xffffffffu, s0, 2);
            s1 += __shfl_xor_sync(0xffffffffu, s1, 1);
            s1 += __shfl_xor_sync(0xffffffffu, s1, 2);
            lv[2 * mt] = lv[2 * mt] * al0 + s0;
            lv[2 * mt + 1] = lv[2 * mt + 1] * al1 + s1;
            mr[2 * mt] = mn0; mr[2 * mt + 1] = mn1;
#pragma unroll
            for (int nt = 0; nt < 8; nt++) {
                o[mt][nt][0] *= al0; o[mt][nt][1] *= al0;
                o[mt][nt][2] *= al1; o[mt][nt][3] *= al1;
            }
        }

#pragma unroll
        for (int j = 0; j < 4; j++) {
            uint32_t ph[2][4], pl[2][4];
#pragma unroll
            for (int mt = 0; mt < 2; mt++) {
                split2(sc[mt][2 * j][0],     sc[mt][2 * j][1],     ph[mt][0], pl[mt][0]);
                split2(sc[mt][2 * j][2],     sc[mt][2 * j][3],     ph[mt][1], pl[mt][1]);
                split2(sc[mt][2 * j + 1][0], sc[mt][2 * j + 1][1], ph[mt][2], pl[mt][2]);
                split2(sc[mt][2 * j + 1][2], sc[mt][2 * j + 1][3], ph[mt][3], pl[mt][3]);
            }
            int krow = j * 16 + ((part & 1) << 3) + (lane & 7);
#pragma unroll
            for (int g16 = 0; g16 < 4; g16++) {
                int nb = g16 * 16 + ((part >> 1) << 3);
                uint32_t off = SWZ(krow * 128 + nb * 2);
                uint32_t v0, v1, v2, v3;
                LDSM4T(v0, v1, v2, v3, vH + off);
#pragma unroll
                for (int mt = 0; mt < 2; mt++) {
                    MMA(o[mt][2 * g16],     ph[mt], v0, v1);
                    MMA(o[mt][2 * g16 + 1], ph[mt], v2, v3);
                    MMA(o[mt][2 * g16],     pl[mt], v0, v1);
                    MMA(o[mt][2 * g16 + 1], pl[mt], v2, v3);
                }
                LDSM4T(v0, v1, v2, v3, vL + off);
#pragma unroll
                for (int mt = 0; mt < 2; mt++) {
                    MMA(o[mt][2 * g16],     ph[mt], v0, v1);
                    MMA(o[mt][2 * g16 + 1], ph[mt], v2, v3);
                }
            }
        }
        __syncthreads();
        ISSUE(t + 2);
    }

#pragma unroll
    for (int mt = 0; mt < 2; mt++) {
        const float i0 = 1.f / lv[2 * mt], i1 = 1.f / lv[2 * mt + 1];
        const int r0 = q0 + wrow + mt * 16 + g, r1 = r0 + 8;
#pragma unroll
        for (int nt = 0; nt < 8; nt++) {
            int col = h * 64 + nt * 8 + t4 * 2;
            uint32_t hh, ll;
            split2(o[mt][nt][0] * i0, o[mt][nt][1] * i0, hh, ll);
            size_t o0 = (size_t)(b * S_ + r0) * D_ + col;
            *(uint32_t*)(Oh + o0) = hh; *(uint32_t*)(Ol + o0) = ll;
            split2(o[mt][nt][2] * i1, o[mt][nt][3] * i1, hh, ll);
            size_t o1 = (size_t)(b * S_ + r1) * D_ + col;
            *(uint32_t*)(Oh + o1) = hh; *(uint32_t*)(Ol + o1) = ll;
        }
    }
}

// ---------------------------------------------------------------------------
// MEGA kernel, stage order K -> V -> Q -> attn -> O-proj
//   bid 0..255    K proj
//   bid 256..511  V proj
//   bid 512..767  Q proj
//   bid 768..1279 attention
//   bid 1280..1535 O proj
// ---------------------------------------------------------------------------
struct MegaP {
    const bf16 *xh, *xl, *wh, *wl;
    const float *bq, *bk, *bv, *bo;
    bf16 *qh, *ql, *kh, *kl, *vh, *vl, *ah, *al;
    float *out;
};

__global__ __launch_bounds__(128, 2) void mega(MegaP P)
{
    extern __shared__ char smem[];
    const int bid = blockIdx.x;
    const int tid = threadIdx.x;
    const int WN = D_ * D_;

    if (bid < 768) {
        // ---- projections; s: 0=K, 1=V, 2=Q
        const int s = bid >> 8, r = bid & 255;
        const int n0 = (r & 7) * 128, m0 = (r >> 3) * 128;
        const int z = (s == 0) ? 1 : (s == 1) ? 2 : 0;   // weight index: Wq=0,Wk=1,Wv=2
        const bf16* Wh = P.wh + (size_t)z * WN;
        const bf16* Wl = P.wl + (size_t)z * WN;
        const float* bias = (s == 0) ? P.bk : (s == 1) ? P.bv : P.bq;
        bf16* Oh = (s == 0) ? P.kh : (s == 1) ? P.vh : P.qh;
        bf16* Ol = (s == 0) ? P.kl : (s == 1) ? P.vl : P.ql;
        const float sc = (s == 2) ? QSCALE : 1.f;
        proj_body(smem, P.xh, P.xl, Wh, Wl, bias, Oh, Ol, nullptr, sc, 0, m0, n0, 0);
        __threadfence();
        __syncthreads();
        if (tid == 0) {
            if (s == 2) atomicAdd(&g_fq[(m0 >> 7) * 8 + (n0 >> 7)], 1);
            else        atomicAdd(&g_fkv[(m0 >> 11) * 8 + (n0 >> 7)], 1);
        }
    } else if (bid < 1280) {
        // ---- attention
        const int id = bid - 768;
        const int qt = id & 15, h = (id >> 4) & 15, b = id >> 8;
        const int my = b * 16 + qt, nt = h >> 1;
        waitflag(&g_fq[my * 8 + nt], 1);
        waitflag(&g_fkv[b * 8 + nt], 32);
        attn_body(smem, P.qh, P.ql, P.kh, P.kl, P.vh, P.vl, P.ah, P.al, b, h, qt * 128);
        __threadfence();
        __syncthreads();
        if (tid == 0) atomicAdd(&g_fa[my], 1);
    } else {
        // ---- output projection
        const int id = bid - 1280;
        const int n0 = (id & 7) * 128, my = id >> 3, m0 = my * 128;
        waitflag(&g_fa[my], 16);
        proj_body(smem, P.ah, P.al, P.wh + (size_t)3 * WN, P.wl + (size_t)3 * WN,
                  P.bo, nullptr, nullptr, P.out, 1.f, 1, m0, n0, 256);
    }
}

// ---------------------------------------------------------------------------
// Launch
// ---------------------------------------------------------------------------
extern "C" void kernel_launch(void* const* d_in, const int* in_sizes, int n_in,
                              void* d_out, int out_size)
{
    const float* x  = (const float*)d_in[0];
    const float* Wq = (const float*)d_in[1];
    const float* bq = (const float*)d_in[2];
    const float* Wk = (const float*)d_in[3];
    const float* bk = (const float*)d_in[4];
    const float* Wv = (const float*)d_in[5];
    const float* bv = (const float*)d_in[6];
    const float* Wo = (const float*)d_in[7];
    const float* bo = (const float*)d_in[8];
    float* out = (float*)d_out;

    bf16 *xh, *xl, *wh, *wl, *qh, *ql, *kh, *kl, *vh, *vl, *ah, *al;
    cudaGetSymbolAddress((void**)&xh, g_xh); cudaGetSymbolAddress((void**)&xl, g_xl);
    cudaGetSymbolAddress((void**)&wh, g_wh); cudaGetSymbolAddress((void**)&wl, g_wl);
    cudaGetSymbolAddress((void**)&qh, g_qh); cudaGetSymbolAddress((void**)&ql, g_ql);
    cudaGetSymbolAddress((void**)&kh, g_kh); cudaGetSymbolAddress((void**)&kl, g_kl);
    cudaGetSymbolAddress((void**)&vh, g_vh); cudaGetSymbolAddress((void**)&vl, g_vl);
    cudaGetSymbolAddress((void**)&ah, g_ah); cudaGetSymbolAddress((void**)&al, g_al);

    const int WN = D_ * D_;
    cvt_kernel<<<M_ * D_ / 4 / 256, 256>>>(x, xh, xl, M_ * D_ / 4);
    {
        CvtW C;
        C.src[0] = Wq; C.src[1] = Wk; C.src[2] = Wv; C.src[3] = Wo;
        C.hi = wh; C.lo = wl;
        dim3 g(WN / 4 / 256, 4);
        cvtw_kernel<<<g, 256>>>(C);
    }

    cudaFuncSetAttribute(mega, cudaFuncAttributeMaxDynamicSharedMemorySize, PJ_SMEM);

    {
        MegaP P;
        P.xh = xh; P.xl = xl; P.wh = wh; P.wl = wl;
        P.bq = bq; P.bk = bk; P.bv = bv; P.bo = bo;
        P.qh = qh; P.ql = ql; P.kh = kh; P.kl = kl;
        P.vh = vh; P.vl = vl; P.ah = ah; P.al = al;
        P.out = out;
        mega<<<1536, 128, PJ_SMEM>>>(P);
    }
}